// round 5
// baseline (speedup 1.0000x reference)
#include <cuda_runtime.h>

// 14-qubit, 5-layer variational circuit, batch 2048. One CTA (1024 threads)
// per batch element; state = interleaved complex float2[16384] (128 KB smem).
// Layer = 4 register rounds of 4 local qubits each (16 amps/thread, 8 f32x2
// packs). Single global GF(2) layout sigma(j)=j^((j>>4)&15) keeps every
// access bank-conflict-free; rounds B/C/D are in-place (no pre-scatter
// barrier). CNOT ring (prefix-XOR linear map) fused into round-A's gather;
// layer 0 closed form; measurement fused into the last round.

#define NQ 14
#define NL 5
#define NA 6
#define NSTATE 16384
#define NT 1024

typedef unsigned long long ull;

// ---------- packed f32x2 helpers ----------
__device__ __forceinline__ ull pk(float lo, float hi) {
    ull r; asm("mov.b64 %0, {%1, %2};" : "=l"(r) : "f"(lo), "f"(hi)); return r;
}
__device__ __forceinline__ void upk(ull v, float& lo, float& hi) {
    asm("mov.b64 {%0, %1}, %2;" : "=f"(lo), "=f"(hi) : "l"(v));
}
__device__ __forceinline__ ull f2mul(ull a, ull b) {
    ull d; asm("mul.rn.f32x2 %0, %1, %2;" : "=l"(d) : "l"(a), "l"(b)); return d;
}
__device__ __forceinline__ ull f2fma(ull a, ull b, ull c) {
    ull d; asm("fma.rn.f32x2 %0, %1, %2, %3;" : "=l"(d) : "l"(a), "l"(b), "l"(c)); return d;
}
__device__ __forceinline__ ull swpl(ull v) {
    float a, b; upk(v, a, b); return pk(b, a);
}

struct Gate  { ull ar, ai, br, bi, nai, nbr, nbi; };
struct GateM { ull nai_ai, ai_nai, br_nbr; };

__device__ __forceinline__ void apply2(const Gate& g, ull& a0r, ull& a0i,
                                       ull& a1r, ull& a1i) {
    ull n0r = f2fma(g.br,  a1r, f2fma(g.nbi, a1i, f2fma(g.nai, a0i, f2mul(g.ar,  a0r))));
    ull n0i = f2fma(g.bi,  a1r, f2fma(g.br,  a1i, f2fma(g.ai,  a0r, f2mul(g.ar,  a0i))));
    ull n1r = f2fma(g.ai,  a1i, f2fma(g.ar,  a1r, f2fma(g.nbi, a0i, f2mul(g.nbr, a0r))));
    ull n1i = f2fma(g.nai, a1r, f2fma(g.ar,  a1i, f2fma(g.bi,  a0r, f2mul(g.nbr, a0i))));
    a0r = n0r; a0i = n0i; a1r = n1r; a1i = n1i;
}

// Gate on the SIMD lane bit: butterfly between the two lanes of each pack.
__device__ __forceinline__ void apply_mixed(const Gate& g, const GateM& gm,
                                            ull& Pr, ull& Pi) {
    const ull Qr = swpl(Pr), Qi = swpl(Pi);
    ull Nr = f2fma(g.nbi,     Qi, f2fma(gm.br_nbr, Qr, f2fma(gm.nai_ai, Pi, f2mul(g.ar,      Pr))));
    ull Ni = f2fma(gm.br_nbr, Qi, f2fma(g.bi,      Qr, f2fma(g.ar,      Pi, f2mul(gm.ai_nai, Pr))));
    Pr = Nr; Pi = Ni;
}

// ---------- GF(2)-linear index maps ----------
// Forward ring (14 CNOTs): d[k]=j[0]^..^j[k] (k>=1), d[0]=parity(j[1..13])
__device__ constexpr int ringf(int x) {
    int y = x;
    y ^= y << 1; y ^= y << 2; y ^= y << 4; y ^= y << 8;
    y &= 0x3FFF;
    return (y & 0x3FFE) | (((y >> 13) ^ x) & 1);
}
__device__ constexpr int ringinv(int d) {
    int m  = (d ^ (d << 1)) & 0x3FFC;
    int m0 = ((d >> 13) ^ d) & 1;
    int m1 = ((d >> 13) ^ (d >> 1) ^ d) & 1;
    return m | m0 | (m1 << 1);
}
__device__ constexpr int sig(int j) { return j ^ ((j >> 4) & 15); }

__global__ void __launch_bounds__(NT, 1)
qcirc_kernel(const float* __restrict__ x,        // [B, 14]
             const float* __restrict__ iscale,   // [5, 28]
             const float* __restrict__ wts,      // [5, 28]
             const float* __restrict__ ascale,   // [6]
             const float* __restrict__ abias,    // [6]
             float* __restrict__ out)            // [B, 6]
{
    extern __shared__ float2 st[];               // [NSTATE] 128 KB
    __shared__ Gate  s_g[NL][NQ];
    __shared__ GateM s_gm[NL][3];                // qubits 3, 7, 11
    __shared__ float s_u0[NQ][4];
    __shared__ float s_red[NT / 32][NA];

    const int t = threadIdx.x;
    const int b = blockIdx.x;

    // ---- all layers' fused gate tables: U = RY(beta) RZ(gamma) RY(alpha)
    if (t < NL * NQ) {
        const int l = t / NQ, i = t % NQ;
        const float xi = x[b * NQ + i];
        const float* isl = iscale + l * 2 * NQ;
        const float* wl  = wts    + l * 2 * NQ;
        const float alpha = isl[i] * xi;
        const float gamma = isl[NQ + i] * xi + wl[i];
        const float beta  = wl[NQ + i];
        float sa, ca, sg, cg, sb, cb;
        sincosf(0.5f * alpha, &sa, &ca);
        sincosf(0.5f * gamma, &sg, &cg);
        sincosf(0.5f * beta,  &sb, &cb);
        const float cc = cb * ca, ss = sb * sa;
        const float cs = cb * sa, sc = sb * ca;
        const float ar =  cg * (cc - ss);
        const float ai = -sg * (cc + ss);
        const float br = -cg * (cs + sc);
        const float bi =  sg * (cs - sc);
        Gate gg;
        gg.ar = pk(ar, ar);   gg.ai = pk(ai, ai);
        gg.br = pk(br, br);   gg.bi = pk(bi, bi);
        gg.nai = pk(-ai, -ai); gg.nbr = pk(-br, -br); gg.nbi = pk(-bi, -bi);
        s_g[l][i] = gg;
        if (i == 3 || i == 7 || i == 11) {
            GateM gm;
            gm.nai_ai = pk(-ai, ai);
            gm.ai_nai = pk(ai, -ai);
            gm.br_nbr = pk(br, -br);
            s_gm[l][i >> 2] = gm;
        }
        if (l == 0) {
            s_u0[i][0] = ar; s_u0[i][1] = ai; s_u0[i][2] = br; s_u0[i][3] = bi;
        }
    }
    __syncthreads();

    // ---- per-thread bases ----
    const int gA = sig(ringinv(t << 4));              // round-A gather base
    const int sA = sig(t << 4);                       // round-A scatter base
    const int bB = sig((t & 15) | ((t >> 4) << 8));   // round-B base
    const int bC = sig((t & 255) | ((t >> 8) << 12)); // round-C base
    const int bD = sig(t);                            // round-D base
    const int rt_m = ringf(t);                        // measurement base

    float acc[NA];
    #pragma unroll
    for (int a = 0; a < NA; ++a) acc[a] = 0.0f;

    // ---- layer 0: pre-ring product state, closed form --------------------
    {
        float Pr0 = 1.0f, Pi0 = 0.0f;
        #pragma unroll
        for (int q = 0; q < 10; ++q) {
            const int bq = (t >> q) & 1;
            const float fr = bq ? -s_u0[q][2] : s_u0[q][0];
            const float fi = bq ?  s_u0[q][3] : s_u0[q][1];
            const float nr = Pr0 * fr - Pi0 * fi;
            Pi0 = Pr0 * fi + Pi0 * fr;
            Pr0 = nr;
        }
        float cr[16], ci[16];
        cr[0] = Pr0; ci[0] = Pi0;
        #pragma unroll
        for (int bb = 0; bb < 4; ++bb) {
            const float a0r = s_u0[10 + bb][0], a0i = s_u0[10 + bb][1];
            const float f1r = -s_u0[10 + bb][2], f1i = s_u0[10 + bb][3];
            #pragma unroll
            for (int c = 0; c < (1 << bb); ++c) {
                const float tr = cr[c], ti = ci[c];
                cr[c] = tr * a0r - ti * a0i;
                ci[c] = tr * a0i + ti * a0r;
                cr[c | (1 << bb)] = tr * f1r - ti * f1i;
                ci[c | (1 << bb)] = tr * f1i + ti * f1r;
            }
        }
        #pragma unroll
        for (int c = 0; c < 16; ++c)
            st[bD ^ (c << 10)] = make_float2(cr[c], ci[c]);   // sig(t | c<<10)
    }
    __syncthreads();

    ull Pr[8], Pi[8];
    #pragma unroll 1
    for (int l = 1; l < NL; ++l) {
        // ===== round A: logical qubits 0..3 (prev layer's ring fused) =====
        #pragma unroll
        for (int p = 0; p < 8; ++p) {
            const float2 A = st[gA ^ sig(ringinv(p))];
            const float2 B = st[gA ^ sig(ringinv(p | 8))];
            Pr[p] = pk(A.x, B.x); Pi[p] = pk(A.y, B.y);
        }
        __syncthreads();                              // all gathers done
        #pragma unroll
        for (int bb = 0; bb < 3; ++bb) {
            const Gate g = s_g[l][bb];
            const int bit = 1 << bb;
            #pragma unroll
            for (int n = 0; n < 4; ++n) {
                const int lo = ((n & ~(bit - 1)) << 1) | (n & (bit - 1));
                apply2(g, Pr[lo], Pi[lo], Pr[lo | bit], Pi[lo | bit]);
            }
        }
        {
            const Gate g = s_g[l][3];
            const GateM gm = s_gm[l][0];
            #pragma unroll
            for (int p = 0; p < 8; ++p) apply_mixed(g, gm, Pr[p], Pi[p]);
        }
        #pragma unroll
        for (int p = 0; p < 8; ++p) {
            float x0, x1, y0, y1;
            upk(Pr[p], x0, x1); upk(Pi[p], y0, y1);
            st[sA ^ p]       = make_float2(x0, y0);   // sig((t<<4)|p)
            st[sA ^ (p | 8)] = make_float2(x1, y1);
        }
        __syncthreads();

        // ===== round B: qubits 4..7 (in-place) ============================
        #pragma unroll
        for (int p = 0; p < 8; ++p) {
            const float2 A = st[bB ^ (p << 4) ^ p];
            const float2 B = st[bB ^ ((p | 8) << 4) ^ (p | 8)];
            Pr[p] = pk(A.x, B.x); Pi[p] = pk(A.y, B.y);
        }
        #pragma unroll
        for (int bb = 0; bb < 3; ++bb) {
            const Gate g = s_g[l][4 + bb];
            const int bit = 1 << bb;
            #pragma unroll
            for (int n = 0; n < 4; ++n) {
                const int lo = ((n & ~(bit - 1)) << 1) | (n & (bit - 1));
                apply2(g, Pr[lo], Pi[lo], Pr[lo | bit], Pi[lo | bit]);
            }
        }
        {
            const Gate g = s_g[l][7];
            const GateM gm = s_gm[l][1];
            #pragma unroll
            for (int p = 0; p < 8; ++p) apply_mixed(g, gm, Pr[p], Pi[p]);
        }
        #pragma unroll
        for (int p = 0; p < 8; ++p) {
            float x0, x1, y0, y1;
            upk(Pr[p], x0, x1); upk(Pi[p], y0, y1);
            st[bB ^ (p << 4) ^ p]             = make_float2(x0, y0);
            st[bB ^ ((p | 8) << 4) ^ (p | 8)] = make_float2(x1, y1);
        }
        __syncthreads();

        // ===== round C: qubits 8..11 (in-place) ===========================
        #pragma unroll
        for (int p = 0; p < 8; ++p) {
            const float2 A = st[bC ^ (p << 8)];
            const float2 B = st[bC ^ ((p | 8) << 8)];
            Pr[p] = pk(A.x, B.x); Pi[p] = pk(A.y, B.y);
        }
        #pragma unroll
        for (int bb = 0; bb < 3; ++bb) {
            const Gate g = s_g[l][8 + bb];
            const int bit = 1 << bb;
            #pragma unroll
            for (int n = 0; n < 4; ++n) {
                const int lo = ((n & ~(bit - 1)) << 1) | (n & (bit - 1));
                apply2(g, Pr[lo], Pi[lo], Pr[lo | bit], Pi[lo | bit]);
            }
        }
        {
            const Gate g = s_g[l][11];
            const GateM gm = s_gm[l][2];
            #pragma unroll
            for (int p = 0; p < 8; ++p) apply_mixed(g, gm, Pr[p], Pi[p]);
        }
        #pragma unroll
        for (int p = 0; p < 8; ++p) {
            float x0, x1, y0, y1;
            upk(Pr[p], x0, x1); upk(Pi[p], y0, y1);
            st[bC ^ (p << 8)]       = make_float2(x0, y0);
            st[bC ^ ((p | 8) << 8)] = make_float2(x1, y1);
        }
        __syncthreads();

        // ===== round D: qubits 12..13 (in-place; lane bit = qubit 10) =====
        // pack p bits: p0 = logical 11 (passive), p1 = q12, p2 = q13
        #pragma unroll
        for (int p = 0; p < 8; ++p) {
            const float2 A = st[bD ^ (p << 11)];
            const float2 B = st[bD ^ (p << 11) ^ (1 << 10)];
            Pr[p] = pk(A.x, B.x); Pi[p] = pk(A.y, B.y);
        }
        #pragma unroll
        for (int bb = 1; bb < 3; ++bb) {
            const Gate g = s_g[l][11 + bb];
            const int bit = 1 << bb;
            #pragma unroll
            for (int n = 0; n < 4; ++n) {
                const int lo = ((n & ~(bit - 1)) << 1) | (n & (bit - 1));
                apply2(g, Pr[lo], Pi[lo], Pr[lo | bit], Pi[lo | bit]);
            }
        }
        if (l < NL - 1) {
            #pragma unroll
            for (int p = 0; p < 8; ++p) {
                float x0, x1, y0, y1;
                upk(Pr[p], x0, x1); upk(Pi[p], y0, y1);
                st[bD ^ (p << 11)]             = make_float2(x0, y0);
                st[bD ^ (p << 11) ^ (1 << 10)] = make_float2(x1, y1);
            }
            __syncthreads();
        } else {
            // ---- measurement fused with the final ring -------------------
            // lane1 index = lane0 ^ ringf(1<<10) = lane0 ^ 0x3C01:
            // only Z_0's sign differs between lanes.
            #pragma unroll
            for (int p = 0; p < 8; ++p) {
                const ull Pp = f2fma(Pi[p], Pi[p], f2mul(Pr[p], Pr[p]));
                float p0, p1;
                upk(Pp, p0, p1);
                const int d0 = rt_m ^ ringf(p << 11);
                const float sum = p0 + p1, dif = p0 - p1;
                acc[0] += (d0 & 1) ? -dif : dif;
                #pragma unroll
                for (int a = 1; a < NA; ++a)
                    acc[a] += ((d0 >> a) & 1) ? -sum : sum;
            }
        }
    }

    // ---- block reduction of <Z_a> ----------------------------------------
    #pragma unroll
    for (int a = 0; a < NA; ++a) {
        #pragma unroll
        for (int off = 16; off; off >>= 1)
            acc[a] += __shfl_xor_sync(0xffffffffu, acc[a], off);
    }
    const int lane = t & 31, warp = t >> 5;
    if (lane == 0) {
        #pragma unroll
        for (int a = 0; a < NA; ++a) s_red[warp][a] = acc[a];
    }
    __syncthreads();
    if (t < NA) {
        float s = 0.0f;
        #pragma unroll
        for (int w = 0; w < NT / 32; ++w) s += s_red[w][t];
        out[b * NA + t] = s * ascale[t] + abias[t];
    }
}

extern "C" void kernel_launch(void* const* d_in, const int* in_sizes, int n_in,
                              void* d_out, int out_size) {
    const float* x      = (const float*)d_in[0];
    const float* iscale = (const float*)d_in[1];
    const float* wts    = (const float*)d_in[2];
    const float* ascale = (const float*)d_in[3];
    const float* abias  = (const float*)d_in[4];
    float* out = (float*)d_out;
    const int B = in_sizes[0] / NQ;

    const size_t shmem = (size_t)NSTATE * sizeof(float2);   // 128 KB
    cudaFuncSetAttribute(qcirc_kernel,
                         cudaFuncAttributeMaxDynamicSharedMemorySize,
                         (int)shmem);
    qcirc_kernel<<<B, NT, shmem>>>(x, iscale, wts, ascale, abias, out);
}

// round 6
// speedup vs baseline: 1.2579x; 1.2579x over previous
#include <cuda_runtime.h>

// 14-qubit, 5-layer variational circuit, batch 2048. One CTA (512 threads)
// per batch element. State stored as lane-pair arrays R[8192]/I[8192] of
// float2 in 128 KB smem: element pair = amplitudes differing in canonical
// bit 13 = the two lanes of an f32x2 pack, so rounds B/C/D move packs with
// single LDS.64/STS.64 (zero repacking movs). Four in-place register rounds
// per layer (q0-3 with ring fused into the gather / q4-7 / q8-11 / q12-13),
// GF(2) swizzle keeps all accesses conflict-free. Layer 0 closed form;
// measurement fused into the last round.

#define NQ 14
#define NL 5
#define NA 6
#define NT 512

typedef unsigned long long ull;

// ---------- packed f32x2 helpers ----------
__device__ __forceinline__ ull pk(float lo, float hi) {
    ull r; asm("mov.b64 %0, {%1, %2};" : "=l"(r) : "f"(lo), "f"(hi)); return r;
}
__device__ __forceinline__ void upk(ull v, float& lo, float& hi) {
    asm("mov.b64 {%0, %1}, %2;" : "=f"(lo), "=f"(hi) : "l"(v));
}
__device__ __forceinline__ ull f2mul(ull a, ull b) {
    ull d; asm("mul.rn.f32x2 %0, %1, %2;" : "=l"(d) : "l"(a), "l"(b)); return d;
}
__device__ __forceinline__ ull f2fma(ull a, ull b, ull c) {
    ull d; asm("fma.rn.f32x2 %0, %1, %2, %3;" : "=l"(d) : "l"(a), "l"(b), "l"(c)); return d;
}
__device__ __forceinline__ ull swpl(ull v) {
    float a, b; upk(v, a, b); return pk(b, a);
}

struct Gate  { ull ar, ai, br, bi, nai, nbr, nbi; };
struct GateM { ull nai_ai, ai_nai, br_nbr; };

__device__ __forceinline__ void apply2(const Gate& g, ull& a0r, ull& a0i,
                                       ull& a1r, ull& a1i) {
    ull n0r = f2fma(g.br,  a1r, f2fma(g.nbi, a1i, f2fma(g.nai, a0i, f2mul(g.ar,  a0r))));
    ull n0i = f2fma(g.bi,  a1r, f2fma(g.br,  a1i, f2fma(g.ai,  a0r, f2mul(g.ar,  a0i))));
    ull n1r = f2fma(g.ai,  a1i, f2fma(g.ar,  a1r, f2fma(g.nbi, a0i, f2mul(g.nbr, a0r))));
    ull n1i = f2fma(g.nai, a1r, f2fma(g.ar,  a1i, f2fma(g.bi,  a0r, f2mul(g.nbr, a0i))));
    a0r = n0r; a0i = n0i; a1r = n1r; a1i = n1i;
}

// Gate on the SIMD lane bit (canonical qubit 13).
__device__ __forceinline__ void apply_mixed(const Gate& g, const GateM& gm,
                                            ull& Pr, ull& Pi) {
    const ull Qr = swpl(Pr), Qi = swpl(Pi);
    ull Nr = f2fma(g.nbi,     Qi, f2fma(gm.br_nbr, Qr, f2fma(gm.nai_ai, Pi, f2mul(g.ar,      Pr))));
    ull Ni = f2fma(gm.br_nbr, Qi, f2fma(g.bi,      Qr, f2fma(g.ar,      Pi, f2mul(gm.ai_nai, Pr))));
    Pr = Nr; Pi = Ni;
}

// ---------- GF(2)-linear index maps ----------
__device__ constexpr int ringf14(int x) {
    int y = x;
    y ^= y << 1; y ^= y << 2; y ^= y << 4; y ^= y << 8;
    y &= 0x3FFF;
    return (y & 0x3FFE) | (((y >> 13) ^ x) & 1);
}
__device__ constexpr int ringinv14(int d) {
    int m  = (d ^ (d << 1)) & 0x3FFC;
    int m0 = ((d >> 13) ^ d) & 1;
    int m1 = ((d >> 13) ^ (d >> 1) ^ d) & 1;
    return m | m0 | (m1 << 1);
}
__device__ constexpr int sg13(int j) { return j ^ ((j >> 4) & 15); }
// per-pack offsets (compile-time after unroll)
__device__ constexpr int OA(int c) { return sg13(ringinv14(c) & 0x1FFF); }
__device__ constexpr int OB(int c) { return (c << 4) ^ c; }
__device__ constexpr int OC(int c) { return c << 8; }
__device__ constexpr int OD(int c) { return (c & 7) | ((c >> 3) << 12); }
__device__ constexpr int RF(int c) { return ringf14((c & 7) | ((c >> 3) << 12)); }

__global__ void __launch_bounds__(NT, 1)
qcirc_kernel(const float* __restrict__ x,        // [B, 14]
             const float* __restrict__ iscale,   // [5, 28]
             const float* __restrict__ wts,      // [5, 28]
             const float* __restrict__ ascale,   // [6]
             const float* __restrict__ abias,    // [6]
             float* __restrict__ out)            // [B, 6]
{
    extern __shared__ float2 sm2[];              // [16384] = 128 KB
    float2* R2 = sm2;                            // [8192] re pairs (b13 lanes)
    float2* I2 = sm2 + 8192;                     // [8192] im pairs
    ull* Rp = reinterpret_cast<ull*>(R2);
    ull* Ip = reinterpret_cast<ull*>(I2);

    __shared__ Gate  s_g[NL][NQ];
    __shared__ GateM s_gm[NL];                   // qubit 13 per layer
    __shared__ float s_u0[NQ][4];
    __shared__ float s_red[NT / 32][NA];

    const int t = threadIdx.x;
    const int b = blockIdx.x;

    // ---- fused gate tables for all layers: U = RY(beta) RZ(gamma) RY(alpha)
    if (t < NL * NQ) {
        const int l = t / NQ, i = t % NQ;
        const float xi = x[b * NQ + i];
        const float* isl = iscale + l * 2 * NQ;
        const float* wl  = wts    + l * 2 * NQ;
        const float alpha = isl[i] * xi;
        const float gamma = isl[NQ + i] * xi + wl[i];
        const float beta  = wl[NQ + i];
        float sa, ca, sg, cg, sb, cb;
        sincosf(0.5f * alpha, &sa, &ca);
        sincosf(0.5f * gamma, &sg, &cg);
        sincosf(0.5f * beta,  &sb, &cb);
        const float cc = cb * ca, ss = sb * sa;
        const float cs = cb * sa, sc = sb * ca;
        const float ar =  cg * (cc - ss);
        const float ai = -sg * (cc + ss);
        const float br = -cg * (cs + sc);
        const float bi =  sg * (cs - sc);
        Gate gg;
        gg.ar = pk(ar, ar);   gg.ai = pk(ai, ai);
        gg.br = pk(br, br);   gg.bi = pk(bi, bi);
        gg.nai = pk(-ai, -ai); gg.nbr = pk(-br, -br); gg.nbi = pk(-bi, -bi);
        s_g[l][i] = gg;
        if (i == 13) {
            GateM gm;
            gm.nai_ai = pk(-ai, ai);
            gm.ai_nai = pk(ai, -ai);
            gm.br_nbr = pk(br, -br);
            s_gm[l] = gm;
        }
        if (l == 0) {
            s_u0[i][0] = ar; s_u0[i][1] = ai; s_u0[i][2] = br; s_u0[i][3] = bi;
        }
    }
    __syncthreads();

    // ---- per-thread bases ----
    const int aF  = ringinv14(t << 4);           // round-A gather source
    const int pA  = sg13(aF & 0x1FFF);
    const int t8  = (aF >> 13) & 1;              // warp-uniform lane select
    const int sAp = sg13(t << 4);                // round-A scatter base
    const int pB  = (t & 15) | ((t >> 4) << 8);  // sg13 is identity here
    const int pC  = sg13((t & 255) | ((t >> 8) << 12));
    const int pD  = sg13(t << 3);
    const int rngD = ringf14(t << 3);            // measurement base

    float acc[NA];
    #pragma unroll
    for (int a = 0; a < NA; ++a) acc[a] = 0.0f;

    // ---- layer 0: pre-ring product state, closed form --------------------
    {
        // base product over qubits 3..11 (bits 0..8 of t)
        float Pr0 = 1.0f, Pi0 = 0.0f;
        #pragma unroll
        for (int k = 0; k < 9; ++k) {
            const int q = 3 + k;
            const int bq = (t >> k) & 1;
            const float fr = bq ? -s_u0[q][2] : s_u0[q][0];
            const float fi = bq ?  s_u0[q][3] : s_u0[q][1];
            const float nr = Pr0 * fr - Pi0 * fi;
            Pi0 = Pr0 * fi + Pi0 * fr;
            Pr0 = nr;
        }
        float cr[16], ci[16];
        cr[0] = Pr0; ci[0] = Pi0;
        const int ebq[4] = {0, 1, 2, 12};        // expansion bits -> qubits
        #pragma unroll
        for (int e = 0; e < 4; ++e) {
            const int q = ebq[e];
            const float a0r = s_u0[q][0], a0i = s_u0[q][1];
            const float f1r = -s_u0[q][2], f1i = s_u0[q][3];
            #pragma unroll
            for (int c = 0; c < (1 << e); ++c) {
                const float tr = cr[c], ti = ci[c];
                cr[c] = tr * a0r - ti * a0i;
                ci[c] = tr * a0i + ti * a0r;
                cr[c | (1 << e)] = tr * f1r - ti * f1i;
                ci[c | (1 << e)] = tr * f1i + ti * f1r;
            }
        }
        // lane factors for qubit 13
        const float g0r = s_u0[13][0], g0i = s_u0[13][1];
        const float g1r = -s_u0[13][2], g1i = s_u0[13][3];
        #pragma unroll
        for (int c = 0; c < 16; ++c) {
            const int a = pD ^ OD(c);
            const float l0r = cr[c] * g0r - ci[c] * g0i;
            const float l0i = cr[c] * g0i + ci[c] * g0r;
            const float l1r = cr[c] * g1r - ci[c] * g1i;
            const float l1i = cr[c] * g1i + ci[c] * g1r;
            Rp[a] = pk(l0r, l1r);
            Ip[a] = pk(l0i, l1i);
        }
    }
    __syncthreads();

    ull Pr[16], Pi[16];
    #pragma unroll 1
    for (int l = 1; l < NL; ++l) {
        // ===== round A: qubits 0..3, previous layer's ring fused ==========
        #pragma unroll
        for (int c = 0; c < 16; ++c) {
            const int a0 = pA ^ OA(c);
            const float2 r0 = R2[a0], r1 = R2[a0 ^ 3];
            const float2 i0 = I2[a0], i1 = I2[a0 ^ 3];
            Pr[c] = t8 ? pk(r0.y, r1.x) : pk(r0.x, r1.y);
            Pi[c] = t8 ? pk(i0.y, i1.x) : pk(i0.x, i1.y);
        }
        __syncthreads();                          // all reads before writes
        #pragma unroll
        for (int bb = 0; bb < 4; ++bb) {
            const Gate g = s_g[l][bb];
            const int bit = 1 << bb;
            #pragma unroll
            for (int n = 0; n < 8; ++n) {
                const int lo = ((n & ~(bit - 1)) << 1) | (n & (bit - 1));
                apply2(g, Pr[lo], Pi[lo], Pr[lo | bit], Pi[lo | bit]);
            }
        }
        #pragma unroll
        for (int c = 0; c < 16; ++c) {
            Rp[sAp ^ c] = Pr[c];
            Ip[sAp ^ c] = Pi[c];
        }
        __syncthreads();

        // ===== round B: qubits 4..7 (in-place) ============================
        #pragma unroll
        for (int c = 0; c < 16; ++c) {
            const int a = pB ^ OB(c);
            Pr[c] = Rp[a]; Pi[c] = Ip[a];
        }
        #pragma unroll
        for (int bb = 0; bb < 4; ++bb) {
            const Gate g = s_g[l][4 + bb];
            const int bit = 1 << bb;
            #pragma unroll
            for (int n = 0; n < 8; ++n) {
                const int lo = ((n & ~(bit - 1)) << 1) | (n & (bit - 1));
                apply2(g, Pr[lo], Pi[lo], Pr[lo | bit], Pi[lo | bit]);
            }
        }
        #pragma unroll
        for (int c = 0; c < 16; ++c) {
            const int a = pB ^ OB(c);
            Rp[a] = Pr[c]; Ip[a] = Pi[c];
        }
        __syncthreads();

        // ===== round C: qubits 8..11 (in-place) ===========================
        #pragma unroll
        for (int c = 0; c < 16; ++c) {
            const int a = pC ^ OC(c);
            Pr[c] = Rp[a]; Pi[c] = Ip[a];
        }
        #pragma unroll
        for (int bb = 0; bb < 4; ++bb) {
            const Gate g = s_g[l][8 + bb];
            const int bit = 1 << bb;
            #pragma unroll
            for (int n = 0; n < 8; ++n) {
                const int lo = ((n & ~(bit - 1)) << 1) | (n & (bit - 1));
                apply2(g, Pr[lo], Pi[lo], Pr[lo | bit], Pi[lo | bit]);
            }
        }
        #pragma unroll
        for (int c = 0; c < 16; ++c) {
            const int a = pC ^ OC(c);
            Rp[a] = Pr[c]; Ip[a] = Pi[c];
        }
        __syncthreads();

        // ===== round D: qubits 12 (pack bit 3) and 13 (lane), in-place ====
        #pragma unroll
        for (int c = 0; c < 16; ++c) {
            const int a = pD ^ OD(c);
            Pr[c] = Rp[a]; Pi[c] = Ip[a];
        }
        {
            const Gate g = s_g[l][12];
            #pragma unroll
            for (int n = 0; n < 8; ++n)
                apply2(g, Pr[n], Pi[n], Pr[n | 8], Pi[n | 8]);
        }
        {
            const Gate g = s_g[l][13];
            const GateM gm = s_gm[l];
            #pragma unroll
            for (int c = 0; c < 16; ++c) apply_mixed(g, gm, Pr[c], Pi[c]);
        }
        if (l < NL - 1) {
            #pragma unroll
            for (int c = 0; c < 16; ++c) {
                const int a = pD ^ OD(c);
                Rp[a] = Pr[c]; Ip[a] = Pi[c];
            }
            __syncthreads();
        } else {
            // ---- measurement fused with the final (owed) ring ------------
            // lane1 logical index = lane0 ^ ringf(1<<13) = ^0x2001:
            // only Z_0 differs between lanes.
            #pragma unroll
            for (int c = 0; c < 16; ++c) {
                const ull Pp = f2fma(Pi[c], Pi[c], f2mul(Pr[c], Pr[c]));
                float p0, p1;
                upk(Pp, p0, p1);
                const int d0 = rngD ^ RF(c);
                const float sum = p0 + p1, dif = p0 - p1;
                acc[0] += (d0 & 1) ? -dif : dif;
                #pragma unroll
                for (int a = 1; a < NA; ++a)
                    acc[a] += ((d0 >> a) & 1) ? -sum : sum;
            }
        }
    }

    // ---- block reduction of <Z_a> ----------------------------------------
    #pragma unroll
    for (int a = 0; a < NA; ++a) {
        #pragma unroll
        for (int off = 16; off; off >>= 1)
            acc[a] += __shfl_xor_sync(0xffffffffu, acc[a], off);
    }
    const int lane = t & 31, warp = t >> 5;
    if (lane == 0) {
        #pragma unroll
        for (int a = 0; a < NA; ++a) s_red[warp][a] = acc[a];
    }
    __syncthreads();
    if (t < NA) {
        float s = 0.0f;
        #pragma unroll
        for (int w = 0; w < NT / 32; ++w) s += s_red[w][t];
        out[b * NA + t] = s * ascale[t] + abias[t];
    }
}

extern "C" void kernel_launch(void* const* d_in, const int* in_sizes, int n_in,
                              void* d_out, int out_size) {
    const float* x      = (const float*)d_in[0];
    const float* iscale = (const float*)d_in[1];
    const float* wts    = (const float*)d_in[2];
    const float* ascale = (const float*)d_in[3];
    const float* abias  = (const float*)d_in[4];
    float* out = (float*)d_out;
    const int B = in_sizes[0] / NQ;

    const size_t shmem = (size_t)16384 * sizeof(float2);   // 128 KB
    cudaFuncSetAttribute(qcirc_kernel,
                         cudaFuncAttributeMaxDynamicSharedMemorySize,
                         (int)shmem);
    qcirc_kernel<<<B, NT, shmem>>>(x, iscale, wts, ascale, abias, out);
}